// round 7
// baseline (speedup 1.0000x reference)
#include <cuda_runtime.h>
#include <cuda_bf16.h>
#include <cstdint>

#define NUM_DST   10000
#define NUM_EDGES 600000
#define DN   100
#define DE   172
#define DTF  100
#define DOUT 128
#define KDIM (DN + DE + DTF)   // 372
#define NKC  12                // k-chunks of 32
#define CH   64                // edges per work item
#define MAXITEMS (NUM_EDGES / CH + NUM_DST)   // 19375

// ---------------- scratch ----------------------------------------------------
__device__ float  g_qnodes[NUM_DST * DOUT];
__device__ float  g_qbk[NUM_DST * 2];
__device__ float  g_Pq[(size_t)NUM_DST * KDIM * 2];
__device__ float2 g_U[(size_t)NUM_DST * KDIM];     // [d][k] -> (head0, head1)
__device__ float  g_z[NUM_DST * 2];
__device__ float  g_agg[NUM_DST * DOUT];
__device__ float  g_qbias[DOUT];
__device__ float  g_absum[2];
__device__ int    g_cnt[NUM_DST];
__device__ int    g_start[NUM_DST + 1];
__device__ int    g_ofs[NUM_DST];
__device__ int    g_perm[NUM_EDGES];
__device__ int    g_items[MAXITEMS];
__device__ int    g_nitems;

// ---------------- kernel 0: init + derived constants -------------------------
__global__ void init_kernel(const float* __restrict__ time_b,
                            const float* __restrict__ wq,
                            const float* __restrict__ bq,
                            const float* __restrict__ att_bias)
{
    int idx = blockIdx.x * blockDim.x + threadIdx.x;
    if (idx < NUM_DST * KDIM) g_U[idx] = make_float2(0.f, 0.f);
    if (idx < NUM_DST) g_cnt[idx] = 0;
    if (idx < NUM_DST * 2) g_z[idx] = 0.f;
    if (idx == 0) g_nitems = 0;
    if (idx < DOUT) {
        float acc = bq[idx];
        #pragma unroll 4
        for (int t = 0; t < DTF; t++)
            acc += cosf(time_b[t]) * wq[(DN + t) * DOUT + idx];
        g_qbias[idx] = acc;
    }
    if (idx < 2) {
        float s = 0.f;
        for (int j = 0; j < DOUT / 2; j++) s += att_bias[idx * (DOUT / 2) + j];
        g_absum[idx] = s;
    }
}

// ---------------- sort pass 1: histogram -------------------------------------
__global__ void hist_kernel(const int* __restrict__ dst_idx)
{
    int e = blockIdx.x * blockDim.x + threadIdx.x;
    if (e < NUM_EDGES) atomicAdd(&g_cnt[dst_idx[e]], 1);
}

// ---------------- sort pass 2: exclusive scan (1 block, 1024 thr) ------------
__global__ __launch_bounds__(1024) void scan_kernel()
{
    __shared__ int wsum[32];
    int t = threadIdx.x;
    int lane = t & 31, w = t >> 5;
    int base = t * 10;
    int loc[10], s = 0;
    #pragma unroll
    for (int i = 0; i < 10; i++) {
        int idx = base + i;
        loc[i] = s;
        s += (idx < NUM_DST) ? g_cnt[idx] : 0;
    }
    int pre = s;
    #pragma unroll
    for (int off = 1; off < 32; off <<= 1) {
        int n = __shfl_up_sync(0xffffffffu, pre, off);
        if (lane >= off) pre += n;
    }
    if (lane == 31) wsum[w] = pre;
    __syncthreads();
    if (w == 0) {
        int v = wsum[lane];
        int p = v;
        #pragma unroll
        for (int off = 1; off < 32; off <<= 1) {
            int n = __shfl_up_sync(0xffffffffu, p, off);
            if (lane >= off) p += n;
        }
        wsum[lane] = p - v;
    }
    __syncthreads();
    int texcl = pre - s + wsum[w];
    #pragma unroll
    for (int i = 0; i < 10; i++) {
        int idx = base + i;
        if (idx < NUM_DST) {
            int v = texcl + loc[i];
            g_start[idx] = v;
            g_ofs[idx]   = v;
        }
    }
    if (t == 1023) g_start[NUM_DST] = texcl + s;
}

// ---------------- sort pass 3: scatter ---------------------------------------
__global__ void scatter_kernel(const int* __restrict__ dst_idx)
{
    int e = blockIdx.x * blockDim.x + threadIdx.x;
    if (e < NUM_EDGES) {
        int pos = atomicAdd(&g_ofs[dst_idx[e]], 1);
        g_perm[pos] = e;
    }
}

// ---------------- work items: (dst, chunk) pairs ------------------------------
__global__ void items_kernel()
{
    int d = blockIdx.x * blockDim.x + threadIdx.x;
    if (d >= NUM_DST) return;
    int cnt = g_start[d + 1] - g_start[d];
    int nch = (cnt + CH - 1) / CH;
    if (nch > 0) {
        int base = atomicAdd(&g_nitems, nch);
        for (int c = 0; c < nch; c++)
            g_items[base + c] = (d << 5) | c;
    }
}

// ---------------- kernel 1: Q per dst node (4 dst / block) + Q.bk ------------
__global__ __launch_bounds__(128) void qnode_kernel(const float* __restrict__ h,
                                                    const float* __restrict__ wq,
                                                    const float* __restrict__ bk)
{
    int dbase = blockIdx.x * 4;
    int c = threadIdx.x;
    __shared__ float sh[4][DN];
    __shared__ float part[4][4];
    for (int i = c; i < 4 * DN; i += 128) {
        int dl = i / DN, k = i - dl * DN;
        sh[dl][k] = h[(size_t)(dbase + dl) * DN + k];
    }
    __syncthreads();
    float qb = g_qbias[c];
    float a[4] = {qb, qb, qb, qb};
    #pragma unroll 4
    for (int k = 0; k < DN; k++) {
        float w = wq[k * DOUT + c];
        #pragma unroll
        for (int d = 0; d < 4; d++) a[d] = fmaf(sh[d][k], w, a[d]);
    }
    #pragma unroll
    for (int d = 0; d < 4; d++)
        g_qnodes[(dbase + d) * DOUT + c] = a[d];

    float bkc = bk[c];
    float p[4];
    #pragma unroll
    for (int d = 0; d < 4; d++) p[d] = a[d] * bkc;
    #pragma unroll
    for (int off = 16; off > 0; off >>= 1)
        #pragma unroll
        for (int d = 0; d < 4; d++)
            p[d] += __shfl_xor_sync(0xffffffffu, p[d], off);
    int warp = c >> 5;
    if ((c & 31) == 0)
        #pragma unroll
        for (int d = 0; d < 4; d++) part[d][warp] = p[d];
    __syncthreads();
    if (c < 8) {
        int d = c >> 1, hh = c & 1;
        g_qbk[(dbase + d) * 2 + hh] = part[d][hh * 2] + part[d][hh * 2 + 1];
    }
}

// ---------------- kernel 1b: Pq[d,k,h] = sum_c qn[d,64h+c] * wk[k,64h+c] -----
__global__ __launch_bounds__(256) void pq_kernel(const float* __restrict__ wk)
{
    __shared__ float qs[64][129];
    __shared__ float ws[64][129];
    int dbase = blockIdx.x * 64;
    int kbase = blockIdx.y * 64;
    int tid = threadIdx.x;
    for (int i = tid; i < 64 * 128; i += 256) {
        int r = i >> 7, c = i & 127;
        int d = dbase + r;
        qs[r][c] = (d < NUM_DST) ? g_qnodes[d * DOUT + c] : 0.f;
        int k = kbase + r;
        ws[r][c] = (k < KDIM) ? wk[k * DOUT + c] : 0.f;
    }
    __syncthreads();
    int tx = tid & 15, ty = tid >> 4;
    float acc[2][4][4];
    #pragma unroll
    for (int hh = 0; hh < 2; hh++)
        #pragma unroll
        for (int i = 0; i < 4; i++)
            #pragma unroll
            for (int j = 0; j < 4; j++) acc[hh][i][j] = 0.f;

    #pragma unroll 1
    for (int hh = 0; hh < 2; hh++) {
        for (int c = 0; c < 64; c++) {
            float q[4], w[4];
            #pragma unroll
            for (int i = 0; i < 4; i++) q[i] = qs[ty * 4 + i][hh * 64 + c];
            #pragma unroll
            for (int j = 0; j < 4; j++) w[j] = ws[tx * 4 + j][hh * 64 + c];
            #pragma unroll
            for (int i = 0; i < 4; i++)
                #pragma unroll
                for (int j = 0; j < 4; j++)
                    acc[hh][i][j] = fmaf(q[i], w[j], acc[hh][i][j]);
        }
    }
    #pragma unroll
    for (int i = 0; i < 4; i++) {
        int d = dbase + ty * 4 + i;
        if (d >= NUM_DST) continue;
        #pragma unroll
        for (int j = 0; j < 4; j++) {
            int k = kbase + tx * 4 + j;
            if (k >= KDIM) continue;
            g_Pq[((size_t)d * KDIM + k) * 2 + 0] = acc[0][i][j];
            g_Pq[((size_t)d * KDIM + k) * 2 + 1] = acc[1][i][j];
        }
    }
}

// ---------------- kernel 2: block-per-item score + exp + z + U ---------------
// Item = (dst, 64-edge chunk). 8 warps, warp-per-edge (<=8 each). Pq in smem,
// per-warp U in regs, 8-way smem reduce, one red.global.add flush per item.
__global__ __launch_bounds__(256) void scoreU_kernel(
    const float* __restrict__ h,   const float* __restrict__ ef,
    const float* __restrict__ dt,
    const float* __restrict__ time_w, const float* __restrict__ time_b)
{
    __shared__ float sPq[KDIM * 2];
    __shared__ float sU[8][KDIM * 2];
    __shared__ float sZ[8][2];
    if (blockIdx.x >= g_nitems) return;
    int v_it = g_items[blockIdx.x];
    int d = v_it >> 5, chunk = v_it & 31;
    int i0 = g_start[d] + chunk * CH;
    int i1 = min(g_start[d + 1], i0 + CH);

    const int tid = threadIdx.x;
    const int lane = tid & 31;
    const int wid = tid >> 5;

    for (int i = tid; i < KDIM * 2; i += 256)
        sPq[i] = g_Pq[(size_t)d * KDIM * 2 + i];
    __syncthreads();

    // per-lane Pq fragment -> registers
    float2 p[NKC];
    #pragma unroll
    for (int it = 0; it < NKC; it++) {
        int k = it * 32 + lane;
        p[it] = (k < KDIM) ? *(const float2*)(sPq + k * 2)
                           : make_float2(0.f, 0.f);
    }
    float2 u[NKC];
    #pragma unroll
    for (int it = 0; it < NKC; it++) u[it] = make_float2(0.f, 0.f);
    float z0 = 0.f, z1 = 0.f;
    const float sb0 = g_absum[0] + g_qbk[d * 2 + 0];
    const float sb1 = g_absum[1] + g_qbk[d * 2 + 1];

    for (int i = i0 + wid; i < i1; i += 8) {
        int e = g_perm[i];
        float td = dt[e];
        const float* __restrict__ hrow  = h + (size_t)(NUM_DST + e) * DN;
        const float* __restrict__ efrow = ef + (size_t)e * DE;
        float v[NKC];
        #pragma unroll
        for (int it = 0; it < NKC; it++) {
            int k = it * 32 + lane;
            float x = 0.f;
            if (k < DN)            x = hrow[k];
            else if (k < DN + DE)  x = efrow[k - DN];
            else if (k < KDIM) { int t = k - DN - DE; x = __cosf(td * time_w[t] + time_b[t]); }
            v[it] = x;
        }
        float a0 = 0.f, a1 = 0.f;
        #pragma unroll
        for (int it = 0; it < NKC; it++) {
            a0 = fmaf(v[it], p[it].x, a0);
            a1 = fmaf(v[it], p[it].y, a1);
        }
        #pragma unroll
        for (int off = 16; off > 0; off >>= 1) {
            a0 += __shfl_xor_sync(0xffffffffu, a0, off);
            a1 += __shfl_xor_sync(0xffffffffu, a1, off);
        }
        float s0 = a0 + sb0;
        float s1 = a1 + sb1;
        s0 = s0 > 0.f ? s0 : 0.2f * s0;
        s1 = s1 > 0.f ? s1 : 0.2f * s1;
        float e0 = __expf(fminf(s0, 80.f));
        float e1 = __expf(fminf(s1, 80.f));
        z0 += e0; z1 += e1;
        #pragma unroll
        for (int it = 0; it < NKC; it++) {
            u[it].x = fmaf(v[it], e0, u[it].x);
            u[it].y = fmaf(v[it], e1, u[it].y);
        }
    }

    // stash per-warp partials
    #pragma unroll
    for (int it = 0; it < NKC; it++) {
        int k = it * 32 + lane;
        if (k < KDIM) *(float2*)(&sU[wid][k * 2]) = u[it];
    }
    if (lane == 0) { sZ[wid][0] = z0; sZ[wid][1] = z1; }
    __syncthreads();

    // 8-way reduce + global flush
    for (int j = tid; j < KDIM * 2; j += 256) {
        float s = sU[0][j];
        #pragma unroll
        for (int w = 1; w < 8; w++) s += sU[w][j];
        asm volatile("red.global.add.f32 [%0], %1;"
                     :: "l"((float*)g_U + (size_t)d * KDIM * 2 + j), "f"(s)
                     : "memory");
    }
    if (tid < 2) {
        float s = sZ[0][tid];
        #pragma unroll
        for (int w = 1; w < 8; w++) s += sZ[w][tid];
        atomicAdd(&g_z[d * 2 + tid], s);
    }
}

// ---------------- kernel 3: agg = (U/z) @ wv + bv  (8 dst / block) -----------
__global__ __launch_bounds__(128) void aggmm_kernel(const float* __restrict__ wv,
                                                    const float* __restrict__ bv)
{
    int dbase = blockIdx.x * 8;
    int c = threadIdx.x;
    int hh = c >> 6;
    __shared__ float sU[8][KDIM * 2];
    __shared__ float sZ[8][2];

    if (c < 16) {
        int d = c >> 1, j = c & 1;
        sZ[d][j] = g_z[(dbase + d) * 2 + j];
    }
    __syncthreads();
    for (int i = c; i < 8 * KDIM * 2; i += 128) {
        int d = i / (KDIM * 2);
        int j = i - d * (KDIM * 2);
        float z = sZ[d][j & 1];
        float u = ((const float*)(g_U + (size_t)(dbase + d) * KDIM))[j];
        sU[d][j] = (z > 0.f) ? (u / z) : 0.f;
    }
    __syncthreads();

    float acc[8];
    #pragma unroll
    for (int d = 0; d < 8; d++) acc[d] = 0.f;
    #pragma unroll 4
    for (int k = 0; k < KDIM; k++) {
        float w = wv[k * DOUT + c];
        #pragma unroll
        for (int d = 0; d < 8; d++)
            acc[d] = fmaf(sU[d][k * 2 + hh], w, acc[d]);
    }
    float bvc = bv[c];
    #pragma unroll
    for (int d = 0; d < 8; d++) {
        float r = (sZ[d][hh] > 0.f) ? (acc[d] + bvc) : 0.f;
        g_agg[(dbase + d) * DOUT + c] = r;
    }
}

// ---------------- kernel 4: output GEMM + relu + layernorm (4 dst/block) -----
__global__ __launch_bounds__(128) void out_kernel(
    const float* __restrict__ h,    const float* __restrict__ wout,
    const float* __restrict__ bout, const float* __restrict__ ln_g,
    const float* __restrict__ ln_b, float* __restrict__ out)
{
    int dbase = blockIdx.x * 4;
    int c = threadIdx.x;
    __shared__ float sin[4][DOUT + DN];
    __shared__ float red1[4][4], red2[4][4];
    for (int i = c; i < 4 * (DOUT + DN); i += 128) {
        int dl = i / (DOUT + DN), k = i - dl * (DOUT + DN);
        int d = dbase + dl;
        float v;
        if (k < DOUT) v = g_agg[d * DOUT + k];
        else          v = h[(size_t)d * DN + (k - DOUT)];
        sin[dl][k] = v;
    }
    __syncthreads();

    float b0 = bout[c];
    float a[4] = {b0, b0, b0, b0};
    #pragma unroll 4
    for (int k = 0; k < DOUT + DN; k++) {
        float w = wout[k * DOUT + c];
        #pragma unroll
        for (int d = 0; d < 4; d++) a[d] = fmaf(sin[d][k], w, a[d]);
    }
    float s1[4], s2[4];
    #pragma unroll
    for (int d = 0; d < 4; d++) {
        a[d] = fmaxf(a[d], 0.f);
        s1[d] = a[d];
        s2[d] = a[d] * a[d];
    }
    #pragma unroll
    for (int off = 16; off > 0; off >>= 1) {
        #pragma unroll
        for (int d = 0; d < 4; d++) {
            s1[d] += __shfl_xor_sync(0xffffffffu, s1[d], off);
            s2[d] += __shfl_xor_sync(0xffffffffu, s2[d], off);
        }
    }
    int warp = c >> 5;
    if ((c & 31) == 0) {
        #pragma unroll
        for (int d = 0; d < 4; d++) { red1[d][warp] = s1[d]; red2[d][warp] = s2[d]; }
    }
    __syncthreads();
    #pragma unroll
    for (int d = 0; d < 4; d++) {
        float t1 = red1[d][0] + red1[d][1] + red1[d][2] + red1[d][3];
        float t2 = red2[d][0] + red2[d][1] + red2[d][2] + red2[d][3];
        float mu  = t1 * (1.f / DOUT);
        float var = t2 * (1.f / DOUT) - mu * mu;
        out[(size_t)(dbase + d) * DOUT + c] =
            (a[d] - mu) * rsqrtf(var + 1e-5f) * ln_g[c] + ln_b[c];
    }
}

// ---------------- launch -----------------------------------------------------
extern "C" void kernel_launch(void* const* d_in, const int* in_sizes, int n_in,
                              void* d_out, int out_size)
{
    int off = (n_in >= 18 && in_sizes[4] == 1) ? 1 : 0;
    const float* h        = (const float*)d_in[0];
    const float* ef       = (const float*)d_in[1];
    const float* dt       = (const float*)d_in[2];
    const int*   dst_idx  = (const int*)  d_in[3];
    const float* time_w   = (const float*)d_in[4 + off];
    const float* time_b   = (const float*)d_in[5 + off];
    const float* wq       = (const float*)d_in[6 + off];
    const float* bq       = (const float*)d_in[7 + off];
    const float* wk       = (const float*)d_in[8 + off];
    const float* bk       = (const float*)d_in[9 + off];
    const float* wv       = (const float*)d_in[10 + off];
    const float* bv       = (const float*)d_in[11 + off];
    const float* att_bias = (const float*)d_in[12 + off];
    const float* wout     = (const float*)d_in[13 + off];
    const float* bout     = (const float*)d_in[14 + off];
    const float* ln_g     = (const float*)d_in[15 + off];
    const float* ln_b     = (const float*)d_in[16 + off];
    float* out = (float*)d_out;

    init_kernel<<<(NUM_DST * KDIM + 255) / 256, 256>>>(time_b, wq, bq, att_bias);
    hist_kernel<<<(NUM_EDGES + 255) / 256, 256>>>(dst_idx);
    scan_kernel<<<1, 1024>>>();
    scatter_kernel<<<(NUM_EDGES + 255) / 256, 256>>>(dst_idx);
    items_kernel<<<(NUM_DST + 255) / 256, 256>>>();
    qnode_kernel<<<NUM_DST / 4, 128>>>(h, wq, bk);
    pq_kernel<<<dim3((NUM_DST + 63) / 64, (KDIM + 63) / 64), 256>>>(wk);
    scoreU_kernel<<<MAXITEMS, 256>>>(h, ef, dt, time_w, time_b);
    aggmm_kernel<<<NUM_DST / 8, 128>>>(wv, bv);
    out_kernel<<<NUM_DST / 4, 128>>>(h, wout, bout, ln_g, ln_b, out);
}

// round 8
// speedup vs baseline: 1.1534x; 1.1534x over previous
#include <cuda_runtime.h>
#include <cuda_fp16.h>
#include <cstdint>

#define NUM_DST   10000
#define NUM_EDGES 600000
#define DN   100
#define DE   172
#define DTF  100
#define DOUT 128
#define KDIM (DN + DE + DTF)   // 372
#define NKC  12                // k-chunks of 32

// ---------------- scratch ----------------------------------------------------
__device__ float   g_qnodes[NUM_DST * DOUT];
__device__ float   g_qbk[NUM_DST * 2];
__device__ __half2 g_Pqh[(size_t)NUM_DST * KDIM];   // [d][k] -> (head0, head1) fp16
__device__ float2  g_U[(size_t)NUM_DST * KDIM];     // [d][k] -> (head0, head1) fp32
__device__ float   g_z[NUM_DST * 2];
__device__ float   g_qbias[DOUT];
__device__ float   g_absum[2];

// ---------------- kernel 0: init + derived constants -------------------------
__global__ void init_kernel(const float* __restrict__ time_b,
                            const float* __restrict__ wq,
                            const float* __restrict__ bq,
                            const float* __restrict__ att_bias)
{
    int idx = blockIdx.x * blockDim.x + threadIdx.x;
    if (idx < NUM_DST * KDIM) g_U[idx] = make_float2(0.f, 0.f);
    if (idx < NUM_DST * 2) g_z[idx] = 0.f;
    if (idx < DOUT) {
        float acc = bq[idx];
        #pragma unroll 4
        for (int t = 0; t < DTF; t++)
            acc += cosf(time_b[t]) * wq[(DN + t) * DOUT + idx];
        g_qbias[idx] = acc;
    }
    if (idx < 2) {
        float s = 0.f;
        for (int j = 0; j < DOUT / 2; j++) s += att_bias[idx * (DOUT / 2) + j];
        g_absum[idx] = s;
    }
}

// ---------------- kernel 1: Q per dst node (4 dst / block) + Q.bk ------------
__global__ __launch_bounds__(128) void qnode_kernel(const float* __restrict__ h,
                                                    const float* __restrict__ wq,
                                                    const float* __restrict__ bk)
{
    int dbase = blockIdx.x * 4;
    int c = threadIdx.x;
    __shared__ float sh[4][DN];
    __shared__ float part[4][4];
    for (int i = c; i < 4 * DN; i += 128) {
        int dl = i / DN, k = i - dl * DN;
        sh[dl][k] = h[(size_t)(dbase + dl) * DN + k];
    }
    __syncthreads();
    float qb = g_qbias[c];
    float a[4] = {qb, qb, qb, qb};
    #pragma unroll 4
    for (int k = 0; k < DN; k++) {
        float w = wq[k * DOUT + c];
        #pragma unroll
        for (int d = 0; d < 4; d++) a[d] = fmaf(sh[d][k], w, a[d]);
    }
    #pragma unroll
    for (int d = 0; d < 4; d++)
        g_qnodes[(dbase + d) * DOUT + c] = a[d];

    // qbk[d][h] = sum_c q[d][c] * bk[c]  (head h = cols 64h..64h+63)
    float bkc = bk[c];
    float p[4];
    #pragma unroll
    for (int d = 0; d < 4; d++) p[d] = a[d] * bkc;
    #pragma unroll
    for (int off = 16; off > 0; off >>= 1)
        #pragma unroll
        for (int d = 0; d < 4; d++)
            p[d] += __shfl_xor_sync(0xffffffffu, p[d], off);
    int warp = c >> 5;
    if ((c & 31) == 0)
        #pragma unroll
        for (int d = 0; d < 4; d++) part[d][warp] = p[d];
    __syncthreads();
    if (c < 8) {
        int d = c >> 1, hh = c & 1;
        g_qbk[(dbase + d) * 2 + hh] = part[d][hh * 2] + part[d][hh * 2 + 1];
    }
}

// ---------------- kernel 1b: Pq[d,k,h] = sum_c qn[d,64h+c] * wk[k,64h+c] -----
// output packed fp16 (both heads in one __half2)
__global__ __launch_bounds__(256) void pq_kernel(const float* __restrict__ wk)
{
    __shared__ float qs[64][129];
    __shared__ float ws[64][129];
    int dbase = blockIdx.x * 64;
    int kbase = blockIdx.y * 64;
    int tid = threadIdx.x;
    for (int i = tid; i < 64 * 128; i += 256) {
        int r = i >> 7, c = i & 127;
        int d = dbase + r;
        qs[r][c] = (d < NUM_DST) ? g_qnodes[d * DOUT + c] : 0.f;
        int k = kbase + r;
        ws[r][c] = (k < KDIM) ? wk[k * DOUT + c] : 0.f;
    }
    __syncthreads();
    int tx = tid & 15, ty = tid >> 4;
    float acc[2][4][4];
    #pragma unroll
    for (int hh = 0; hh < 2; hh++)
        #pragma unroll
        for (int i = 0; i < 4; i++)
            #pragma unroll
            for (int j = 0; j < 4; j++) acc[hh][i][j] = 0.f;

    #pragma unroll 1
    for (int hh = 0; hh < 2; hh++) {
        for (int c = 0; c < 64; c++) {
            float q[4], w[4];
            #pragma unroll
            for (int i = 0; i < 4; i++) q[i] = qs[ty * 4 + i][hh * 64 + c];
            #pragma unroll
            for (int j = 0; j < 4; j++) w[j] = ws[tx * 4 + j][hh * 64 + c];
            #pragma unroll
            for (int i = 0; i < 4; i++)
                #pragma unroll
                for (int j = 0; j < 4; j++)
                    acc[hh][i][j] = fmaf(q[i], w[j], acc[hh][i][j]);
        }
    }
    #pragma unroll
    for (int i = 0; i < 4; i++) {
        int d = dbase + ty * 4 + i;
        if (d >= NUM_DST) continue;
        #pragma unroll
        for (int j = 0; j < 4; j++) {
            int k = kbase + tx * 4 + j;
            if (k >= KDIM) continue;
            g_Pqh[(size_t)d * KDIM + k] =
                __floats2half2_rn(acc[0][i][j], acc[1][i][j]);
        }
    }
}

// ---------------- kernel 2: per-edge warp: score + exp + z + U ---------------
// R5 structure (streaming DRAM, max parallelism); Pq gather in fp16.
__global__ __launch_bounds__(256) void scoreU_kernel(
    const float* __restrict__ h,   const float* __restrict__ ef,
    const float* __restrict__ dt,  const int*   __restrict__ dst_idx,
    const float* __restrict__ time_w, const float* __restrict__ time_b)
{
    int e = (blockIdx.x * 256 + threadIdx.x) >> 5;
    if (e >= NUM_EDGES) return;
    int lane = threadIdx.x & 31;
    float td = dt[e];
    int d = dst_idx[e];
    const float* __restrict__ hrow  = h + (size_t)(NUM_DST + e) * DN;
    const float* __restrict__ efrow = ef + (size_t)e * DE;

    // prefetch all kv values (high MLP)
    float v[NKC];
    #pragma unroll
    for (int it = 0; it < NKC; it++) {
        int k = it * 32 + lane;
        float x = 0.f;
        if (k < DN)            x = __ldg(hrow + k);
        else if (k < DN + DE)  x = __ldg(efrow + k - DN);
        else if (k < KDIM) { int t = k - DN - DE; x = __cosf(td * time_w[t] + time_b[t]); }
        v[it] = x;
    }
    const __half2* __restrict__ pq = g_Pqh + (size_t)d * KDIM;
    float2 p[NKC];
    #pragma unroll
    for (int it = 0; it < NKC; it++) {
        int k = it * 32 + lane;
        p[it] = (k < KDIM) ? __half22float2(__ldg(pq + k))
                           : make_float2(0.f, 0.f);
    }
    float a0 = 0.f, a1 = 0.f;
    #pragma unroll
    for (int it = 0; it < NKC; it++) {
        a0 = fmaf(v[it], p[it].x, a0);
        a1 = fmaf(v[it], p[it].y, a1);
    }
    #pragma unroll
    for (int off = 16; off > 0; off >>= 1) {
        a0 += __shfl_xor_sync(0xffffffffu, a0, off);
        a1 += __shfl_xor_sync(0xffffffffu, a1, off);
    }
    float s0 = a0 + g_absum[0] + g_qbk[d * 2 + 0];
    float s1 = a1 + g_absum[1] + g_qbk[d * 2 + 1];
    s0 = s0 > 0.f ? s0 : 0.2f * s0;
    s1 = s1 > 0.f ? s1 : 0.2f * s1;
    float e0 = __expf(fminf(s0, 80.f));
    float e1 = __expf(fminf(s1, 80.f));
    if (lane == 0) {
        atomicAdd(&g_z[d * 2 + 0], e0);
        atomicAdd(&g_z[d * 2 + 1], e1);
    }
    // U[d][k] += (e0*v, e1*v) — lanes hit consecutive float2s (coalesced)
    float2* __restrict__ Urow = g_U + (size_t)d * KDIM;
    #pragma unroll
    for (int it = 0; it < NKC; it++) {
        int k = it * 32 + lane;
        if (k < KDIM) {
            float ux = v[it] * e0;
            float uy = v[it] * e1;
            asm volatile("red.global.add.v2.f32 [%0], {%1,%2};"
                         :: "l"(Urow + k), "f"(ux), "f"(uy) : "memory");
        }
    }
}

// ---------------- kernel 3: fused agg=(U/z)@wv+bv, out GEMM, relu, LN --------
// 8 dst per 128-thread block.
__global__ __launch_bounds__(128) void outfused_kernel(
    const float* __restrict__ h,    const float* __restrict__ wv,
    const float* __restrict__ bv,   const float* __restrict__ wout,
    const float* __restrict__ bout, const float* __restrict__ ln_g,
    const float* __restrict__ ln_b, float* __restrict__ out)
{
    int dbase = blockIdx.x * 8;
    int c = threadIdx.x;
    int hh = c >> 6;
    __shared__ float sU[8][KDIM * 2];
    __shared__ float sZ[8][2];
    __shared__ float sin[8][DOUT + DN];
    __shared__ float red1[8][4], red2[8][4];

    if (c < 16) {
        int d = c >> 1, j = c & 1;
        sZ[d][j] = g_z[(dbase + d) * 2 + j];
    }
    __syncthreads();
    for (int i = c; i < 8 * KDIM * 2; i += 128) {
        int d = i / (KDIM * 2);
        int j = i - d * (KDIM * 2);
        float z = sZ[d][j & 1];
        float u = ((const float*)(g_U + (size_t)(dbase + d) * KDIM))[j];
        sU[d][j] = (z > 0.f) ? (u / z) : 0.f;
    }
    // stage h rows for the out GEMM while sU is being built
    for (int i = c; i < 8 * DN; i += 128) {
        int d = i / DN, k = i - d * DN;
        sin[d][DOUT + k] = h[(size_t)(dbase + d) * DN + k];
    }
    __syncthreads();

    // agg column c for 8 dsts
    float acc[8];
    #pragma unroll
    for (int d = 0; d < 8; d++) acc[d] = 0.f;
    #pragma unroll 4
    for (int k = 0; k < KDIM; k++) {
        float w = wv[k * DOUT + c];
        #pragma unroll
        for (int d = 0; d < 8; d++)
            acc[d] = fmaf(sU[d][k * 2 + hh], w, acc[d]);
    }
    float bvc = bv[c];
    #pragma unroll
    for (int d = 0; d < 8; d++)
        sin[d][c] = (sZ[d][hh] > 0.f) ? (acc[d] + bvc) : 0.f;
    __syncthreads();

    // out GEMM: column c over concat(agg, h)
    float b0 = bout[c];
    float a[8];
    #pragma unroll
    for (int d = 0; d < 8; d++) a[d] = b0;
    #pragma unroll 4
    for (int k = 0; k < DOUT + DN; k++) {
        float w = wout[k * DOUT + c];
        #pragma unroll
        for (int d = 0; d < 8; d++) a[d] = fmaf(sin[d][k], w, a[d]);
    }
    float s1[8], s2[8];
    #pragma unroll
    for (int d = 0; d < 8; d++) {
        a[d] = fmaxf(a[d], 0.f);
        s1[d] = a[d];
        s2[d] = a[d] * a[d];
    }
    #pragma unroll
    for (int off = 16; off > 0; off >>= 1) {
        #pragma unroll
        for (int d = 0; d < 8; d++) {
            s1[d] += __shfl_xor_sync(0xffffffffu, s1[d], off);
            s2[d] += __shfl_xor_sync(0xffffffffu, s2[d], off);
        }
    }
    int warp = c >> 5;
    if ((c & 31) == 0) {
        #pragma unroll
        for (int d = 0; d < 8; d++) { red1[d][warp] = s1[d]; red2[d][warp] = s2[d]; }
    }
    __syncthreads();
    #pragma unroll
    for (int d = 0; d < 8; d++) {
        float t1 = red1[d][0] + red1[d][1] + red1[d][2] + red1[d][3];
        float t2 = red2[d][0] + red2[d][1] + red2[d][2] + red2[d][3];
        float mu  = t1 * (1.f / DOUT);
        float var = t2 * (1.f / DOUT) - mu * mu;
        out[(size_t)(dbase + d) * DOUT + c] =
            (a[d] - mu) * rsqrtf(var + 1e-5f) * ln_g[c] + ln_b[c];
    }
}

// ---------------- launch -----------------------------------------------------
extern "C" void kernel_launch(void* const* d_in, const int* in_sizes, int n_in,
                              void* d_out, int out_size)
{
    int off = (n_in >= 18 && in_sizes[4] == 1) ? 1 : 0;
    const float* h        = (const float*)d_in[0];
    const float* ef       = (const float*)d_in[1];
    const float* dt       = (const float*)d_in[2];
    const int*   dst_idx  = (const int*)  d_in[3];
    const float* time_w   = (const float*)d_in[4 + off];
    const float* time_b   = (const float*)d_in[5 + off];
    const float* wq       = (const float*)d_in[6 + off];
    const float* bq       = (const float*)d_in[7 + off];
    const float* wk       = (const float*)d_in[8 + off];
    const float* bk       = (const float*)d_in[9 + off];
    const float* wv       = (const float*)d_in[10 + off];
    const float* bv       = (const float*)d_in[11 + off];
    const float* att_bias = (const float*)d_in[12 + off];
    const float* wout     = (const float*)d_in[13 + off];
    const float* bout     = (const float*)d_in[14 + off];
    const float* ln_g     = (const float*)d_in[15 + off];
    const float* ln_b     = (const float*)d_in[16 + off];
    float* out = (float*)d_out;

    init_kernel<<<(NUM_DST * KDIM + 255) / 256, 256>>>(time_b, wq, bq, att_bias);
    qnode_kernel<<<NUM_DST / 4, 128>>>(h, wq, bk);
    pq_kernel<<<dim3((NUM_DST + 63) / 64, (KDIM + 63) / 64), 256>>>(wk);
    scoreU_kernel<<<NUM_EDGES / 8, 256>>>(h, ef, dt, dst_idx, time_w, time_b);
    outfused_kernel<<<NUM_DST / 8, 128>>>(h, wv, bv, wout, bout, ln_g, ln_b, out);
}